// round 12
// baseline (speedup 1.0000x reference)
#include <cuda_runtime.h>

#define NFILT 384      // 3 banks * 128 filters
#define NPTS  2048     // B*H'*W' = 2*32*32
#define KB    96
#define NBINS 97
#define NHB   64       // y-histogram bins (ECDF compression)
#define NUB   256      // u-histogram bins (Bernstein compression)

// ---- scratch (static device globals; no allocation anywhere) ----
__device__ float g_x[NFILT * NPTS];
__device__ float g_y[NFILT * NPTS];
__device__ float g_loss[NFILT];

__device__ __forceinline__ float tanhf_approx(float x) {
    float r; asm("tanh.approx.f32 %0, %1;" : "=f"(r) : "f"(x)); return r;
}

// ============================================================
// Stage 1: register-blocked direct conv, stride 2, zero pad.
// Block = (bank, src, batch, filter-group of 4); 512 thr x 2 pos
// (2x the warps of the 256-thr version -> latency hiding).
// X tile in smem as even/odd column planes [72][2][36] ->
// conflict-free stride-2 taps. Per tap: 4 wgt + 2 patch LDS -> 8 FMA.
// grid: 3 banks * 2 src * 2 batch * 32 groups = 384 blocks.
// ============================================================
template <int KS>
__device__ __forceinline__ void conv_group(
    const float* __restrict__ Xs, const float* __restrict__ Wsh,
    int wsz, int coff, const int* rowbase, float acc[2][4]) {
#pragma unroll
    for (int u = 0; u < KS; u++) {
#pragma unroll
        for (int v = 0; v < KS; v++) {
            int d   = v + 3 - KS / 2;
            int par = d & 1, dc = d >> 1;
            float wreg[4];
#pragma unroll
            for (int ff = 0; ff < 4; ff++)
                wreg[ff] = Wsh[ff * wsz + coff + u * KS + v];
#pragma unroll
            for (int r = 0; r < 2; r++) {
                float p = Xs[rowbase[r] + u * 72 + par * 36 + dc];
#pragma unroll
                for (int ff = 0; ff < 4; ff++)
                    acc[r][ff] = fmaf(wreg[ff], p, acc[r][ff]);
            }
        }
    }
}

__global__ void __launch_bounds__(512) conv_kernel(
    const float* __restrict__ Xg, const float* __restrict__ Xd,
    const float* __restrict__ W3, const float* __restrict__ W5,
    const float* __restrict__ W7) {
    __shared__ float Xs[72 * 72];       // [row][parity][36]
    __shared__ float Wsh[4 * 147];      // 4 filters x 3*KS*KS (max KS=7)

    int bx   = blockIdx.x;
    int bank = bx >> 7;          // 128 blocks per bank
    int rem  = bx & 127;
    int src  = rem >> 6;
    int b    = (rem >> 5) & 1;
    int grp  = rem & 31;         // 32 groups of 4 filters

    const float* X = (src ? Xd : Xg) + b * 12288;
    const float* W;
    int KS;
    if (bank == 0)      { W = W3; KS = 3; }
    else if (bank == 1) { W = W5; KS = 5; }
    else                { W = W7; KS = 7; }
    int wsz = 3 * KS * KS;
    int l0  = grp * 4;

    int t = threadIdx.x;
    for (int i = t; i < 4 * wsz; i += 512)
        Wsh[i] = W[(l0 + i / wsz) * wsz + (i % wsz)];
    for (int i = t; i < 72 * 72; i += 512) Xs[i] = 0.f;

    int rowbase[2];
    int P = KS / 2;
#pragma unroll
    for (int r = 0; r < 2; r++) {
        int idx = t + r * 512;
        int oy = idx >> 5, ox = idx & 31;
        rowbase[r] = (2 * oy + 3 - P) * 72 + ox;
    }

    float acc[2][4];
#pragma unroll
    for (int r = 0; r < 2; r++)
#pragma unroll
        for (int ff = 0; ff < 4; ff++) acc[r][ff] = 0.f;

    for (int c = 0; c < 3; c++) {
        __syncthreads();
        for (int i = t; i < 4096; i += 512) {
            int gr = i >> 6, gc = i & 63;
            int g = gc + 3;
            Xs[(gr + 3) * 72 + (g & 1) * 36 + (g >> 1)] = X[c * 4096 + i];
        }
        __syncthreads();
        int coff = c * KS * KS;
        if (bank == 0)      conv_group<3>(Xs, Wsh, wsz, coff, rowbase, acc);
        else if (bank == 1) conv_group<5>(Xs, Wsh, wsz, coff, rowbase, acc);
        else                conv_group<7>(Xs, Wsh, wsz, coff, rowbase, acc);
    }

    float* outp = src ? g_y : g_x;
#pragma unroll
    for (int ff = 0; ff < 4; ff++) {
        int fg = bank * 128 + l0 + ff;
#pragma unroll
        for (int r = 0; r < 2; r++)
            outp[fg * NPTS + b * 1024 + t + r * 512] = acc[r][ff];
    }
}

// ============================================================
// Stage 2 (fused, one block per filter, 512 threads):
//   tau -> y-histogram (64 bins, centroids, uint32 fixed-point)
//   -> U via weighted tanh -> u-histogram (256 bins, uint32)
//   -> Bernstein p_hat (interleaved conflict-free chunks, 2 accs)
//   -> f_js -> g_loss[f]
// Integer atomics + fixed-order reductions => bit-deterministic.
// ============================================================
__global__ void __launch_bounds__(512) fused_kernel() {
    int f = blockIdx.x;
    int t = threadIdx.x;

    __shared__ float  ys[NPTS];                       // 8KB
    __shared__ float  r1[16], r2[16], r3[16], r4[16];
    __shared__ float  bc[4];                          // c2, bmin, yscale
    __shared__ unsigned ycnt[NHB], ysum[NHB];         // sum scale 2^14
    __shared__ float2 hb[NHB];                        // (-c2*centroid, weight)
    __shared__ unsigned ucnt[NUB], usum[NUB];         // sum scale 2^20
    __shared__ float  ulw[NUB], ul1[NUB], uw[NUB];
    __shared__ float  part[4][NBINS];
    __shared__ float  arr[128];

    for (int i = t; i < NHB; i += 512) { ycnt[i] = 0u; ysum[i] = 0u; }
    for (int i = t; i < NUB; i += 512) { ucnt[i] = 0u; usum[i] = 0u; }

    // ---- load y; accumulate sum/sumsq/min/max ----
    const float* y = g_y + f * NPTS;
    float s = 0.f, ss = 0.f, mn = 1e30f, mx = -1e30f;
    for (int i = t; i < NPTS; i += 512) {
        float v = y[i];
        ys[i] = v;
        s += v; ss = fmaf(v, v, ss);
        mn = fminf(mn, v); mx = fmaxf(mx, v);
    }
    for (int o = 16; o > 0; o >>= 1) {
        s  += __shfl_down_sync(0xffffffffu, s, o);
        ss += __shfl_down_sync(0xffffffffu, ss, o);
        mn  = fminf(mn, __shfl_down_sync(0xffffffffu, mn, o));
        mx  = fmaxf(mx, __shfl_down_sync(0xffffffffu, mx, o));
    }
    int w = t >> 5, lane = t & 31;
    if (lane == 0) { r1[w] = s; r2[w] = ss; r3[w] = mn; r4[w] = mx; }
    __syncthreads();

    if (t == 0) {
        float S = 0.f, SS = 0.f, MN = r3[0], MX = r4[0];
        for (int i = 0; i < 16; i++) {
            S += r1[i]; SS += r2[i];
            MN = fminf(MN, r3[i]); MX = fmaxf(MX, r4[i]);
        }
        float mean = S * (1.f / NPTS);
        float var  = (SS - (float)NPTS * mean * mean) * (1.f / (NPTS - 1));
        float sd   = sqrtf(fmaxf(var, 0.f));
        float scl  = (f < 128) ? 0.3f : (f < 256) ? 0.18f : 0.1f;
        float tau  = scl * (sd + 1e-6f) + 1e-4f;
        bc[0] = 0.5f / tau;
        bc[1] = MN;
        bc[2] = (float)NHB / ((MX - MN) * (1.f + 1e-6f) + 1e-20f);
    }
    __syncthreads();

    float c2 = bc[0], bmin = bc[1], yscale = bc[2];

    // ---- y histogram (uint32 fixed point, q scale 2^14) ----
    for (int i = t; i < NPTS; i += 512) {
        float q = (ys[i] - bmin) * yscale;
        int b = min((int)q, NHB - 1);
        atomicAdd(&ycnt[b], 1u);
        atomicAdd(&ysum[b], (unsigned)(q * 16384.0f + 0.5f));
    }
    __syncthreads();

    for (int b = t; b < NHB; b += 512) {
        unsigned c = ycnt[b];
        float cen = bmin;
        if (c > 0)
            cen = bmin + ((float)ysum[b] / (16384.0f * (float)c)) / yscale;
        hb[b] = make_float2(-c2 * cen, (float)c);
    }
    __syncthreads();

    // ---- U for 4 x-values per thread; u-histogram ----
    const float4 xv = ((const float4*)(g_x + f * NPTS))[t];
    float x0 = xv.x * c2, x1 = xv.y * c2, x2 = xv.z * c2, x3 = xv.w * c2;
    float a0 = 0.f, a1 = 0.f, a2 = 0.f, a3 = 0.f;
#pragma unroll 4
    for (int b = 0; b < NHB; b++) {
        float2 h = hb[b];
        a0 = fmaf(h.y, tanhf_approx(h.x + x0), a0);
        a1 = fmaf(h.y, tanhf_approx(h.x + x1), a1);
        a2 = fmaf(h.y, tanhf_approx(h.x + x2), a2);
        a3 = fmaf(h.y, tanhf_approx(h.x + x3), a3);
    }
#pragma unroll
    for (int q = 0; q < 4; q++) {
        float acc = (q == 0) ? a0 : (q == 1) ? a1 : (q == 2) ? a2 : a3;
        float u = fmaf(acc, 0.5f / NPTS, 0.5f);
        u = fminf(fmaxf(u, 1e-6f), 1.f - 1e-6f);
        int b = min((int)(u * (float)NUB), NUB - 1);
        atomicAdd(&ucnt[b], 1u);
        atomicAdd(&usum[b], (unsigned)(u * 1048576.0f + 0.5f));  // 2^20
    }
    __syncthreads();

    // ---- per-u-bin log terms ----
    for (int b = t; b < NUB; b += 512) {
        unsigned c = ucnt[b];
        if (c > 0) {
            float uc = (float)usum[b] / (1048576.0f * (float)c);
            uc = fminf(fmaxf(uc, 1e-6f), 1.f - 1e-6f);
            ulw[b] = logf(uc);
            ul1[b] = logf(1.f - uc);
            uw[b]  = (float)c;
        } else {
            ulw[b] = -40.f;
            ul1[b] = -40.f;
            uw[b]  = 0.f;
        }
    }
    __syncthreads();

    // ---- Bernstein p_hat partials: 388 threads = 97 n x 4 chunks.
    // Interleaved chunks (b = ch + 4i) -> conflict-free; 2 accs.
    if (t < 4 * NBINS) {
        int n = t >> 2, ch = t & 3;
        float fn = (float)n, kn = (float)(KB - n);
        float logC = lgammaf((float)(KB + 1)) - lgammaf(fn + 1.f) - lgammaf(kn + 1.f);
        float acc0 = 0.f, acc1 = 0.f;
#pragma unroll 4
        for (int i = 0; i < NUB / 8; i++) {
            int b0 = ch + 8 * i;
            int b1 = b0 + 4;
            acc0 += uw[b0] * __expf(fmaf(fn, ulw[b0], fmaf(kn, ul1[b0], logC)));
            acc1 += uw[b1] * __expf(fmaf(fn, ulw[b1], fmaf(kn, ul1[b1], logC)));
        }
        part[ch][n] = acc0 + acc1;
    }
    __syncthreads();

    // ---- f_js per bin, then fixed-order parallel block sum ----
    float val = 0.f;
    if (t < NBINS) {
        float p = part[0][t] + part[1][t] + part[2][t] + part[3][t];
        float ph = p * (1.f / NPTS);
        float v  = fmaxf(ph * (float)NBINS, 1e-12f);
        float wv = 1.f / (1.f + v);
        float term = 0.5f * (1.f + v) *
            (0.6931471805599453f + logf(fmaxf(wv, 1e-12f)) + log1pf(-wv));
        val = term * (1.f / NBINS);
    }
    if (t < 128) arr[t] = (t < NBINS) ? val : 0.f;
    __syncthreads();
    if (t < 32) {
        float a = arr[t] + arr[t + 32] + arr[t + 64] + arr[t + 96];
        for (int o = 16; o > 0; o >>= 1)
            a += __shfl_down_sync(0xffffffffu, a, o);
        if (t == 0) g_loss[f] = a;
    }
}

// ============================================================
// Stage 3: deterministic final reduction
// ============================================================
__global__ void __launch_bounds__(512) reduce_kernel(float* out) {
    int t = threadIdx.x;
    float v = (t < NFILT) ? g_loss[t] : 0.f;
    for (int o = 16; o > 0; o >>= 1) v += __shfl_down_sync(0xffffffffu, v, o);
    __shared__ float sh[16];
    if ((t & 31) == 0) sh[t >> 5] = v;
    __syncthreads();
    if (t == 0) {
        float s = 0.f;
        for (int i = 0; i < 16; i++) s += sh[i];
        out[0] = s * (1.f / 384.f);
    }
}

extern "C" void kernel_launch(void* const* d_in, const int* in_sizes, int n_in,
                              void* d_out, int out_size) {
    const float* Xg = (const float*)d_in[0];
    const float* Xd = (const float*)d_in[1];
    const float* W3 = (const float*)d_in[2];
    const float* W5 = (const float*)d_in[3];
    const float* W7 = (const float*)d_in[4];

    conv_kernel<<<384, 512>>>(Xg, Xd, W3, W5, W7);
    fused_kernel<<<NFILT, 512>>>();
    reduce_kernel<<<1, 512>>>((float*)d_out);
}

// round 14
// speedup vs baseline: 1.1682x; 1.1682x over previous
#include <cuda_runtime.h>

#define NFILT 384      // 3 banks * 128 filters
#define NPTS  2048     // B*H'*W' = 2*32*32
#define KB    96
#define NBINS 97
#define NHB   64       // y-histogram bins (ECDF compression)
#define NUB   256      // u-histogram bins (Bernstein compression)

// ---- scratch (static device globals; no allocation anywhere) ----
__device__ float g_xp[3][NFILT * NPTS];   // per-channel conv partials (fake)
__device__ float g_yp[3][NFILT * NPTS];   // per-channel conv partials (real)
__device__ float g_loss[NFILT];

__device__ __forceinline__ float tanhf_approx(float x) {
    float r; asm("tanh.approx.f32 %0, %1;" : "=f"(r) : "f"(x)); return r;
}

// ============================================================
// Stage 1: register-blocked direct conv, stride 2, zero pad,
// SPLIT BY INPUT CHANNEL (3x blocks -> no K7 tail starvation).
// Block = (bank, channel, src, batch, filter-group of 4);
// 256 thr x 4 pos. X tile in even/odd column planes [72][2][36]
// -> conflict-free stride-2 taps. Per tap: 4 wgt + 4 patch LDS
// -> 16 FMA. grid: 3 banks * 3 ch * 2 src * 2 b * 32 grp = 1152.
// ============================================================
template <int KS>
__device__ __forceinline__ void conv_group(
    const float* __restrict__ Xs, const float* __restrict__ Wsh,
    const int* rowbase, float acc[4][4]) {
    const int KK = KS * KS;
#pragma unroll
    for (int u = 0; u < KS; u++) {
#pragma unroll
        for (int v = 0; v < KS; v++) {
            int d   = v + 3 - KS / 2;
            int par = d & 1, dc = d >> 1;
            float wreg[4];
#pragma unroll
            for (int ff = 0; ff < 4; ff++)
                wreg[ff] = Wsh[ff * KK + u * KS + v];
#pragma unroll
            for (int r = 0; r < 4; r++) {
                float p = Xs[rowbase[r] + u * 72 + par * 36 + dc];
#pragma unroll
                for (int ff = 0; ff < 4; ff++)
                    acc[r][ff] = fmaf(wreg[ff], p, acc[r][ff]);
            }
        }
    }
}

__global__ void __launch_bounds__(256) conv_kernel(
    const float* __restrict__ Xg, const float* __restrict__ Xd,
    const float* __restrict__ W3, const float* __restrict__ W5,
    const float* __restrict__ W7) {
    __shared__ float Xs[72 * 72];       // [row][parity][36]
    __shared__ float Wsh[4 * 49];       // 4 filters x KS*KS (one channel)

    int bx   = blockIdx.x;
    int bank = bx / 384;         // 0..2
    int rem  = bx - bank * 384;
    int c    = rem >> 7;         // channel 0..2
    int r2   = rem & 127;
    int src  = r2 >> 6;
    int b    = (r2 >> 5) & 1;
    int grp  = r2 & 31;          // 32 groups of 4 filters

    const float* X = (src ? Xd : Xg) + b * 12288 + c * 4096;
    const float* W;
    int KS;
    if (bank == 0)      { W = W3; KS = 3; }
    else if (bank == 1) { W = W5; KS = 5; }
    else                { W = W7; KS = 7; }
    int KK  = KS * KS;
    int wsz = 3 * KK;
    int l0  = grp * 4;

    int t = threadIdx.x;
    // weights: channel c slice of 4 filters
    for (int i = t; i < 4 * KK; i += 256)
        Wsh[i] = W[(l0 + i / KK) * wsz + c * KK + (i % KK)];
    for (int i = t; i < 72 * 72; i += 256) Xs[i] = 0.f;
    __syncthreads();
    for (int i = t; i < 4096; i += 256) {
        int gr = i >> 6, gc = i & 63;
        int g = gc + 3;
        Xs[(gr + 3) * 72 + (g & 1) * 36 + (g >> 1)] = X[i];
    }
    __syncthreads();

    int rowbase[4];
    int P = KS / 2;
#pragma unroll
    for (int r = 0; r < 4; r++) {
        int idx = t + r * 256;
        int oy = idx >> 5, ox = idx & 31;
        rowbase[r] = (2 * oy + 3 - P) * 72 + ox;
    }

    float acc[4][4];
#pragma unroll
    for (int r = 0; r < 4; r++)
#pragma unroll
        for (int ff = 0; ff < 4; ff++) acc[r][ff] = 0.f;

    if (bank == 0)      conv_group<3>(Xs, Wsh, rowbase, acc);
    else if (bank == 1) conv_group<5>(Xs, Wsh, rowbase, acc);
    else                conv_group<7>(Xs, Wsh, rowbase, acc);

    float* outp = src ? g_yp[c] : g_xp[c];
#pragma unroll
    for (int ff = 0; ff < 4; ff++) {
        int fg = bank * 128 + l0 + ff;
#pragma unroll
        for (int r = 0; r < 4; r++)
            outp[fg * NPTS + b * 1024 + t + r * 256] = acc[r][ff];
    }
}

// ============================================================
// Stage 2 (fused, one block per filter, 512 threads):
//   sum channel partials (fixed order) -> tau -> y-histogram
//   (64 bins, centroids, uint32 fixed-point) -> U via weighted
//   tanh -> u-histogram (256 bins, uint32) -> Bernstein p_hat
//   (interleaved conflict-free chunks) -> f_js -> g_loss[f]
// Integer atomics + fixed-order reductions => bit-deterministic.
// ============================================================
__global__ void __launch_bounds__(512) fused_kernel() {
    int f = blockIdx.x;
    int t = threadIdx.x;

    __shared__ float  ys[NPTS];                       // 8KB
    __shared__ float  r1[16], r2[16], r3[16], r4[16];
    __shared__ float  bc[4];                          // c2, bmin, yscale
    __shared__ unsigned ycnt[NHB], ysum[NHB];         // sum scale 2^14
    __shared__ float2 hb[NHB];                        // (-c2*centroid, weight)
    __shared__ unsigned ucnt[NUB], usum[NUB];         // sum scale 2^20
    __shared__ float  ulw[NUB], ul1[NUB], uw[NUB];
    __shared__ float  part[4][NBINS];
    __shared__ float  arr[128];

    for (int i = t; i < NHB; i += 512) { ycnt[i] = 0u; ysum[i] = 0u; }
    for (int i = t; i < NUB; i += 512) { ucnt[i] = 0u; usum[i] = 0u; }

    // ---- sum y channel partials (fixed order); stats ----
    const float* y0 = g_yp[0] + f * NPTS;
    const float* y1 = g_yp[1] + f * NPTS;
    const float* y2 = g_yp[2] + f * NPTS;
    float s = 0.f, ss = 0.f, mn = 1e30f, mx = -1e30f;
    for (int i = t; i < NPTS; i += 512) {
        float v = (y0[i] + y1[i]) + y2[i];
        ys[i] = v;
        s += v; ss = fmaf(v, v, ss);
        mn = fminf(mn, v); mx = fmaxf(mx, v);
    }
    for (int o = 16; o > 0; o >>= 1) {
        s  += __shfl_down_sync(0xffffffffu, s, o);
        ss += __shfl_down_sync(0xffffffffu, ss, o);
        mn  = fminf(mn, __shfl_down_sync(0xffffffffu, mn, o));
        mx  = fmaxf(mx, __shfl_down_sync(0xffffffffu, mx, o));
    }
    int w = t >> 5, lane = t & 31;
    if (lane == 0) { r1[w] = s; r2[w] = ss; r3[w] = mn; r4[w] = mx; }
    __syncthreads();

    if (t == 0) {
        float S = 0.f, SS = 0.f, MN = r3[0], MX = r4[0];
        for (int i = 0; i < 16; i++) {
            S += r1[i]; SS += r2[i];
            MN = fminf(MN, r3[i]); MX = fmaxf(MX, r4[i]);
        }
        float mean = S * (1.f / NPTS);
        float var  = (SS - (float)NPTS * mean * mean) * (1.f / (NPTS - 1));
        float sd   = sqrtf(fmaxf(var, 0.f));
        float scl  = (f < 128) ? 0.3f : (f < 256) ? 0.18f : 0.1f;
        float tau  = scl * (sd + 1e-6f) + 1e-4f;
        bc[0] = 0.5f / tau;
        bc[1] = MN;
        bc[2] = (float)NHB / ((MX - MN) * (1.f + 1e-6f) + 1e-20f);
    }
    __syncthreads();

    float c2 = bc[0], bmin = bc[1], yscale = bc[2];

    // ---- y histogram (uint32 fixed point, q scale 2^14) ----
    for (int i = t; i < NPTS; i += 512) {
        float q = (ys[i] - bmin) * yscale;
        int b = min((int)q, NHB - 1);
        atomicAdd(&ycnt[b], 1u);
        atomicAdd(&ysum[b], (unsigned)(q * 16384.0f + 0.5f));
    }
    __syncthreads();

    for (int b = t; b < NHB; b += 512) {
        unsigned c = ycnt[b];
        float cen = bmin;
        if (c > 0)
            cen = bmin + ((float)ysum[b] / (16384.0f * (float)c)) / yscale;
        hb[b] = make_float2(-c2 * cen, (float)c);
    }
    __syncthreads();

    // ---- U for 4 x-values per thread; u-histogram ----
    const float4 xa = ((const float4*)(g_xp[0] + f * NPTS))[t];
    const float4 xb = ((const float4*)(g_xp[1] + f * NPTS))[t];
    const float4 xc = ((const float4*)(g_xp[2] + f * NPTS))[t];
    float x0 = ((xa.x + xb.x) + xc.x) * c2;
    float x1 = ((xa.y + xb.y) + xc.y) * c2;
    float x2 = ((xa.z + xb.z) + xc.z) * c2;
    float x3 = ((xa.w + xb.w) + xc.w) * c2;
    float a0 = 0.f, a1 = 0.f, a2 = 0.f, a3 = 0.f;
#pragma unroll 4
    for (int b = 0; b < NHB; b++) {
        float2 h = hb[b];
        a0 = fmaf(h.y, tanhf_approx(h.x + x0), a0);
        a1 = fmaf(h.y, tanhf_approx(h.x + x1), a1);
        a2 = fmaf(h.y, tanhf_approx(h.x + x2), a2);
        a3 = fmaf(h.y, tanhf_approx(h.x + x3), a3);
    }
#pragma unroll
    for (int q = 0; q < 4; q++) {
        float acc = (q == 0) ? a0 : (q == 1) ? a1 : (q == 2) ? a2 : a3;
        float u = fmaf(acc, 0.5f / NPTS, 0.5f);
        u = fminf(fmaxf(u, 1e-6f), 1.f - 1e-6f);
        int b = min((int)(u * (float)NUB), NUB - 1);
        atomicAdd(&ucnt[b], 1u);
        atomicAdd(&usum[b], (unsigned)(u * 1048576.0f + 0.5f));  // 2^20
    }
    __syncthreads();

    // ---- per-u-bin log terms ----
    for (int b = t; b < NUB; b += 512) {
        unsigned c = ucnt[b];
        if (c > 0) {
            float uc = (float)usum[b] / (1048576.0f * (float)c);
            uc = fminf(fmaxf(uc, 1e-6f), 1.f - 1e-6f);
            ulw[b] = logf(uc);
            ul1[b] = logf(1.f - uc);
            uw[b]  = (float)c;
        } else {
            ulw[b] = -40.f;
            ul1[b] = -40.f;
            uw[b]  = 0.f;
        }
    }
    __syncthreads();

    // ---- Bernstein p_hat partials: 388 threads = 97 n x 4 chunks.
    // Interleaved chunks (b = ch + 4i) -> conflict-free; 2 accs.
    if (t < 4 * NBINS) {
        int n = t >> 2, ch = t & 3;
        float fn = (float)n, kn = (float)(KB - n);
        float logC = lgammaf((float)(KB + 1)) - lgammaf(fn + 1.f) - lgammaf(kn + 1.f);
        float acc0 = 0.f, acc1 = 0.f;
#pragma unroll 4
        for (int i = 0; i < NUB / 8; i++) {
            int b0 = ch + 8 * i;
            int b1 = b0 + 4;
            acc0 += uw[b0] * __expf(fmaf(fn, ulw[b0], fmaf(kn, ul1[b0], logC)));
            acc1 += uw[b1] * __expf(fmaf(fn, ulw[b1], fmaf(kn, ul1[b1], logC)));
        }
        part[ch][n] = acc0 + acc1;
    }
    __syncthreads();

    // ---- f_js per bin, then fixed-order parallel block sum ----
    float val = 0.f;
    if (t < NBINS) {
        float p = part[0][t] + part[1][t] + part[2][t] + part[3][t];
        float ph = p * (1.f / NPTS);
        float v  = fmaxf(ph * (float)NBINS, 1e-12f);
        float wv = 1.f / (1.f + v);
        float term = 0.5f * (1.f + v) *
            (0.6931471805599453f + logf(fmaxf(wv, 1e-12f)) + log1pf(-wv));
        val = term * (1.f / NBINS);
    }
    if (t < 128) arr[t] = (t < NBINS) ? val : 0.f;
    __syncthreads();
    if (t < 32) {
        float a = arr[t] + arr[t + 32] + arr[t + 64] + arr[t + 96];
        for (int o = 16; o > 0; o >>= 1)
            a += __shfl_down_sync(0xffffffffu, a, o);
        if (t == 0) g_loss[f] = a;
    }
}

// ============================================================
// Stage 3: deterministic final reduction
// ============================================================
__global__ void __launch_bounds__(512) reduce_kernel(float* out) {
    int t = threadIdx.x;
    float v = (t < NFILT) ? g_loss[t] : 0.f;
    for (int o = 16; o > 0; o >>= 1) v += __shfl_down_sync(0xffffffffu, v, o);
    __shared__ float sh[16];
    if ((t & 31) == 0) sh[t >> 5] = v;
    __syncthreads();
    if (t == 0) {
        float s = 0.f;
        for (int i = 0; i < 16; i++) s += sh[i];
        out[0] = s * (1.f / 384.f);
    }
}

extern "C" void kernel_launch(void* const* d_in, const int* in_sizes, int n_in,
                              void* d_out, int out_size) {
    const float* Xg = (const float*)d_in[0];
    const float* Xd = (const float*)d_in[1];
    const float* W3 = (const float*)d_in[2];
    const float* W5 = (const float*)d_in[3];
    const float* W7 = (const float*)d_in[4];

    conv_kernel<<<1152, 256>>>(Xg, Xd, W3, W5, W7);
    fused_kernel<<<NFILT, 512>>>();
    reduce_kernel<<<1, 512>>>((float*)d_out);
}

// round 15
// speedup vs baseline: 1.3177x; 1.1280x over previous
#include <cuda_runtime.h>

#define NFILT 384      // 3 banks * 128 filters
#define NPTS  2048     // B*H'*W' = 2*32*32
#define KB    96
#define NBINS 97
#define NHB   32       // y-histogram bins (ECDF compression)
#define NUB   256      // u-histogram bins (Bernstein compression)

// ---- scratch (static device globals; no allocation anywhere) ----
__device__ float g_xp[3][NFILT * NPTS];   // per-channel conv partials (fake)
__device__ float g_yp[3][NFILT * NPTS];   // per-channel conv partials (real)
__device__ float g_loss[NFILT];

__device__ __forceinline__ float tanhf_approx(float x) {
    float r; asm("tanh.approx.f32 %0, %1;" : "=f"(r) : "f"(x)); return r;
}

// ============================================================
// Stage 1: register-blocked direct conv, stride 2, zero pad,
// split by input channel, filter-group of 8.
// Block = (bank, channel, src, batch, group); 256 thr x 4 pos.
// X tile in even/odd column planes [72][2][36] -> conflict-free
// stride-2 taps. Per tap: 8 wgt + 4 patch LDS -> 32 FMA.
// grid: 3 banks * 3 ch * 2 src * 2 b * 16 grp = 576 blocks.
// ============================================================
template <int KS>
__device__ __forceinline__ void conv_group(
    const float* __restrict__ Xs, const float* __restrict__ Wsh,
    const int* rowbase, float acc[4][8]) {
    const int KK = KS * KS;
#pragma unroll
    for (int u = 0; u < KS; u++) {
#pragma unroll
        for (int v = 0; v < KS; v++) {
            int d   = v + 3 - KS / 2;
            int par = d & 1, dc = d >> 1;
            float wreg[8];
#pragma unroll
            for (int ff = 0; ff < 8; ff++)
                wreg[ff] = Wsh[ff * KK + u * KS + v];
#pragma unroll
            for (int r = 0; r < 4; r++) {
                float p = Xs[rowbase[r] + u * 72 + par * 36 + dc];
#pragma unroll
                for (int ff = 0; ff < 8; ff++)
                    acc[r][ff] = fmaf(wreg[ff], p, acc[r][ff]);
            }
        }
    }
}

__global__ void __launch_bounds__(256) conv_kernel(
    const float* __restrict__ Xg, const float* __restrict__ Xd,
    const float* __restrict__ W3, const float* __restrict__ W5,
    const float* __restrict__ W7) {
    __shared__ float Xs[72 * 72];       // [row][parity][36]
    __shared__ float Wsh[8 * 49];       // 8 filters x KS*KS (one channel)

    int bx   = blockIdx.x;
    int bank = bx / 192;         // 0..2
    int rem  = bx - bank * 192;
    int c    = rem >> 6;         // channel 0..2
    int r2   = rem & 63;
    int src  = r2 >> 5;
    int b    = (r2 >> 4) & 1;
    int grp  = r2 & 15;          // 16 groups of 8 filters

    const float* X = (src ? Xd : Xg) + b * 12288 + c * 4096;
    const float* W;
    int KS;
    if (bank == 0)      { W = W3; KS = 3; }
    else if (bank == 1) { W = W5; KS = 5; }
    else                { W = W7; KS = 7; }
    int KK  = KS * KS;
    int wsz = 3 * KK;
    int l0  = grp * 8;

    int t = threadIdx.x;
    for (int i = t; i < 8 * KK; i += 256)
        Wsh[i] = W[(l0 + i / KK) * wsz + c * KK + (i % KK)];
    for (int i = t; i < 72 * 72; i += 256) Xs[i] = 0.f;
    __syncthreads();
    for (int i = t; i < 4096; i += 256) {
        int gr = i >> 6, gc = i & 63;
        int g = gc + 3;
        Xs[(gr + 3) * 72 + (g & 1) * 36 + (g >> 1)] = X[i];
    }
    __syncthreads();

    int rowbase[4];
    int P = KS / 2;
#pragma unroll
    for (int r = 0; r < 4; r++) {
        int idx = t + r * 256;
        int oy = idx >> 5, ox = idx & 31;
        rowbase[r] = (2 * oy + 3 - P) * 72 + ox;
    }

    float acc[4][8];
#pragma unroll
    for (int r = 0; r < 4; r++)
#pragma unroll
        for (int ff = 0; ff < 8; ff++) acc[r][ff] = 0.f;

    if (bank == 0)      conv_group<3>(Xs, Wsh, rowbase, acc);
    else if (bank == 1) conv_group<5>(Xs, Wsh, rowbase, acc);
    else                conv_group<7>(Xs, Wsh, rowbase, acc);

    float* outp = src ? g_yp[c] : g_xp[c];
#pragma unroll
    for (int ff = 0; ff < 8; ff++) {
        int fg = bank * 128 + l0 + ff;
#pragma unroll
        for (int r = 0; r < 4; r++)
            outp[fg * NPTS + b * 1024 + t + r * 256] = acc[r][ff];
    }
}

// ============================================================
// Stage 2 (fused, one block per filter, 512 threads):
//   sum channel partials (fixed order) -> tau -> y-histogram
//   (32 bins, centroids, uint32 fixed-point) -> U via weighted
//   tanh -> u-histogram (256 bins, uint32) -> Bernstein p_hat
//   (interleaved conflict-free chunks) -> f_js -> g_loss[f]
// Integer atomics + fixed-order reductions => bit-deterministic.
// ============================================================
__global__ void __launch_bounds__(512) fused_kernel() {
    int f = blockIdx.x;
    int t = threadIdx.x;

    __shared__ float  ys[NPTS];                       // 8KB
    __shared__ float  r1[16], r2[16], r3[16], r4[16];
    __shared__ float  bc[4];                          // c2, bmin, yscale
    __shared__ unsigned ycnt[NHB], ysum[NHB];         // sum scale 2^14
    __shared__ float2 hb[NHB];                        // (-c2*centroid, weight)
    __shared__ unsigned ucnt[NUB], usum[NUB];         // sum scale 2^20
    __shared__ float  ulw[NUB], ul1[NUB], uw[NUB];
    __shared__ float  part[4][NBINS];
    __shared__ float  arr[128];

    for (int i = t; i < NHB; i += 512) { ycnt[i] = 0u; ysum[i] = 0u; }
    for (int i = t; i < NUB; i += 512) { ucnt[i] = 0u; usum[i] = 0u; }

    // ---- sum y channel partials (fixed order); stats ----
    const float* y0 = g_yp[0] + f * NPTS;
    const float* y1 = g_yp[1] + f * NPTS;
    const float* y2 = g_yp[2] + f * NPTS;
    float s = 0.f, ss = 0.f, mn = 1e30f, mx = -1e30f;
    for (int i = t; i < NPTS; i += 512) {
        float v = (y0[i] + y1[i]) + y2[i];
        ys[i] = v;
        s += v; ss = fmaf(v, v, ss);
        mn = fminf(mn, v); mx = fmaxf(mx, v);
    }
    for (int o = 16; o > 0; o >>= 1) {
        s  += __shfl_down_sync(0xffffffffu, s, o);
        ss += __shfl_down_sync(0xffffffffu, ss, o);
        mn  = fminf(mn, __shfl_down_sync(0xffffffffu, mn, o));
        mx  = fmaxf(mx, __shfl_down_sync(0xffffffffu, mx, o));
    }
    int w = t >> 5, lane = t & 31;
    if (lane == 0) { r1[w] = s; r2[w] = ss; r3[w] = mn; r4[w] = mx; }
    __syncthreads();

    if (t == 0) {
        float S = 0.f, SS = 0.f, MN = r3[0], MX = r4[0];
        for (int i = 0; i < 16; i++) {
            S += r1[i]; SS += r2[i];
            MN = fminf(MN, r3[i]); MX = fmaxf(MX, r4[i]);
        }
        float mean = S * (1.f / NPTS);
        float var  = (SS - (float)NPTS * mean * mean) * (1.f / (NPTS - 1));
        float sd   = sqrtf(fmaxf(var, 0.f));
        float scl  = (f < 128) ? 0.3f : (f < 256) ? 0.18f : 0.1f;
        float tau  = scl * (sd + 1e-6f) + 1e-4f;
        bc[0] = 0.5f / tau;
        bc[1] = MN;
        bc[2] = (float)NHB / ((MX - MN) * (1.f + 1e-6f) + 1e-20f);
    }
    __syncthreads();

    float c2 = bc[0], bmin = bc[1], yscale = bc[2];

    // ---- y histogram (uint32 fixed point, q scale 2^14) ----
    for (int i = t; i < NPTS; i += 512) {
        float q = (ys[i] - bmin) * yscale;
        int b = min((int)q, NHB - 1);
        atomicAdd(&ycnt[b], 1u);
        atomicAdd(&ysum[b], (unsigned)(q * 16384.0f + 0.5f));
    }
    __syncthreads();

    for (int b = t; b < NHB; b += 512) {
        unsigned c = ycnt[b];
        float cen = bmin;
        if (c > 0)
            cen = bmin + ((float)ysum[b] / (16384.0f * (float)c)) / yscale;
        hb[b] = make_float2(-c2 * cen, (float)c);
    }
    __syncthreads();

    // ---- U for 4 x-values per thread; u-histogram ----
    const float4 xa = ((const float4*)(g_xp[0] + f * NPTS))[t];
    const float4 xb = ((const float4*)(g_xp[1] + f * NPTS))[t];
    const float4 xc = ((const float4*)(g_xp[2] + f * NPTS))[t];
    float x0 = ((xa.x + xb.x) + xc.x) * c2;
    float x1 = ((xa.y + xb.y) + xc.y) * c2;
    float x2 = ((xa.z + xb.z) + xc.z) * c2;
    float x3 = ((xa.w + xb.w) + xc.w) * c2;
    float a0 = 0.f, a1 = 0.f, a2 = 0.f, a3 = 0.f;
#pragma unroll
    for (int b = 0; b < NHB; b++) {
        float2 h = hb[b];
        a0 = fmaf(h.y, tanhf_approx(h.x + x0), a0);
        a1 = fmaf(h.y, tanhf_approx(h.x + x1), a1);
        a2 = fmaf(h.y, tanhf_approx(h.x + x2), a2);
        a3 = fmaf(h.y, tanhf_approx(h.x + x3), a3);
    }
#pragma unroll
    for (int q = 0; q < 4; q++) {
        float acc = (q == 0) ? a0 : (q == 1) ? a1 : (q == 2) ? a2 : a3;
        float u = fmaf(acc, 0.5f / NPTS, 0.5f);
        u = fminf(fmaxf(u, 1e-6f), 1.f - 1e-6f);
        int b = min((int)(u * (float)NUB), NUB - 1);
        atomicAdd(&ucnt[b], 1u);
        atomicAdd(&usum[b], (unsigned)(u * 1048576.0f + 0.5f));  // 2^20
    }
    __syncthreads();

    // ---- per-u-bin log terms ----
    for (int b = t; b < NUB; b += 512) {
        unsigned c = ucnt[b];
        if (c > 0) {
            float uc = (float)usum[b] / (1048576.0f * (float)c);
            uc = fminf(fmaxf(uc, 1e-6f), 1.f - 1e-6f);
            ulw[b] = logf(uc);
            ul1[b] = logf(1.f - uc);
            uw[b]  = (float)c;
        } else {
            ulw[b] = -40.f;
            ul1[b] = -40.f;
            uw[b]  = 0.f;
        }
    }
    __syncthreads();

    // ---- Bernstein p_hat partials: 388 threads = 97 n x 4 chunks.
    // Interleaved chunks (b = ch + 4i) -> conflict-free; 2 accs.
    if (t < 4 * NBINS) {
        int n = t >> 2, ch = t & 3;
        float fn = (float)n, kn = (float)(KB - n);
        float logC = lgammaf((float)(KB + 1)) - lgammaf(fn + 1.f) - lgammaf(kn + 1.f);
        float acc0 = 0.f, acc1 = 0.f;
#pragma unroll 4
        for (int i = 0; i < NUB / 8; i++) {
            int b0 = ch + 8 * i;
            int b1 = b0 + 4;
            acc0 += uw[b0] * __expf(fmaf(fn, ulw[b0], fmaf(kn, ul1[b0], logC)));
            acc1 += uw[b1] * __expf(fmaf(fn, ulw[b1], fmaf(kn, ul1[b1], logC)));
        }
        part[ch][n] = acc0 + acc1;
    }
    __syncthreads();

    // ---- f_js per bin, then fixed-order parallel block sum ----
    float val = 0.f;
    if (t < NBINS) {
        float p = part[0][t] + part[1][t] + part[2][t] + part[3][t];
        float ph = p * (1.f / NPTS);
        float v  = fmaxf(ph * (float)NBINS, 1e-12f);
        float wv = 1.f / (1.f + v);
        float term = 0.5f * (1.f + v) *
            (0.6931471805599453f + logf(fmaxf(wv, 1e-12f)) + log1pf(-wv));
        val = term * (1.f / NBINS);
    }
    if (t < 128) arr[t] = (t < NBINS) ? val : 0.f;
    __syncthreads();
    if (t < 32) {
        float a = arr[t] + arr[t + 32] + arr[t + 64] + arr[t + 96];
        for (int o = 16; o > 0; o >>= 1)
            a += __shfl_down_sync(0xffffffffu, a, o);
        if (t == 0) g_loss[f] = a;
    }
}

// ============================================================
// Stage 3: deterministic final reduction
// ============================================================
__global__ void __launch_bounds__(512) reduce_kernel(float* out) {
    int t = threadIdx.x;
    float v = (t < NFILT) ? g_loss[t] : 0.f;
    for (int o = 16; o > 0; o >>= 1) v += __shfl_down_sync(0xffffffffu, v, o);
    __shared__ float sh[16];
    if ((t & 31) == 0) sh[t >> 5] = v;
    __syncthreads();
    if (t == 0) {
        float s = 0.f;
        for (int i = 0; i < 16; i++) s += sh[i];
        out[0] = s * (1.f / 384.f);
    }
}

extern "C" void kernel_launch(void* const* d_in, const int* in_sizes, int n_in,
                              void* d_out, int out_size) {
    const float* Xg = (const float*)d_in[0];
    const float* Xd = (const float*)d_in[1];
    const float* W3 = (const float*)d_in[2];
    const float* W5 = (const float*)d_in[3];
    const float* W7 = (const float*)d_in[4];

    conv_kernel<<<576, 256>>>(Xg, Xd, W3, W5, W7);
    fused_kernel<<<NFILT, 512>>>();
    reduce_kernel<<<1, 512>>>((float*)d_out);
}

// round 16
// speedup vs baseline: 1.3188x; 1.0008x over previous
#include <cuda_runtime.h>

#define NFILT 384      // 3 banks * 128 filters
#define NPTS  2048     // B*H'*W' = 2*32*32
#define KB    96
#define NBINS 97
#define NHB   32       // y-histogram bins (ECDF compression)
#define NUB   256      // u-histogram bins (Bernstein compression)

// ---- scratch (static device globals; no allocation anywhere) ----
__device__ float g_xp[3][NFILT * NPTS];   // per-channel conv partials (fake)
__device__ float g_yp[3][NFILT * NPTS];   // per-channel conv partials (real)
__device__ float g_loss[NFILT];

__device__ __forceinline__ float tanhf_approx(float x) {
    float r; asm("tanh.approx.f32 %0, %1;" : "=f"(r) : "f"(x)); return r;
}

// ============================================================
// Stage 1: register-blocked direct conv, stride 2, zero pad,
// split by input channel, filter-group of 4.
// BANK INTERLEAVED in launch order (bank = bx % 3) so the
// expensive K=7 blocks are co-resident with cheap K=3/K=5
// blocks from wave 1 instead of forming a serial tail.
// Block: 256 thr x 4 pos; X tile in even/odd column planes
// [72][2][36] -> conflict-free stride-2 taps.
// grid: 3 banks * 3 ch * 2 src * 2 b * 32 grp = 1152 blocks.
// ============================================================
template <int KS>
__device__ __forceinline__ void conv_group(
    const float* __restrict__ Xs, const float* __restrict__ Wsh,
    const int* rowbase, float acc[4][4]) {
    const int KK = KS * KS;
#pragma unroll
    for (int u = 0; u < KS; u++) {
#pragma unroll
        for (int v = 0; v < KS; v++) {
            int d   = v + 3 - KS / 2;
            int par = d & 1, dc = d >> 1;
            float wreg[4];
#pragma unroll
            for (int ff = 0; ff < 4; ff++)
                wreg[ff] = Wsh[ff * KK + u * KS + v];
#pragma unroll
            for (int r = 0; r < 4; r++) {
                float p = Xs[rowbase[r] + u * 72 + par * 36 + dc];
#pragma unroll
                for (int ff = 0; ff < 4; ff++)
                    acc[r][ff] = fmaf(wreg[ff], p, acc[r][ff]);
            }
        }
    }
}

__global__ void __launch_bounds__(256) conv_kernel(
    const float* __restrict__ Xg, const float* __restrict__ Xd,
    const float* __restrict__ W3, const float* __restrict__ W5,
    const float* __restrict__ W7) {
    __shared__ float Xs[72 * 72];       // [row][parity][36]
    __shared__ float Wsh[4 * 49];       // 4 filters x KS*KS (one channel)

    int bx   = blockIdx.x;
    int bank = bx % 3;           // INTERLEAVED across launch order
    int rem  = bx / 3;           // 0..383
    int c    = rem >> 7;         // channel 0..2
    int r2   = rem & 127;
    int src  = r2 >> 6;
    int b    = (r2 >> 5) & 1;
    int grp  = r2 & 31;          // 32 groups of 4 filters

    const float* X = (src ? Xd : Xg) + b * 12288 + c * 4096;
    const float* W;
    int KS;
    if (bank == 0)      { W = W3; KS = 3; }
    else if (bank == 1) { W = W5; KS = 5; }
    else                { W = W7; KS = 7; }
    int KK  = KS * KS;
    int wsz = 3 * KK;
    int l0  = grp * 4;

    int t = threadIdx.x;
    for (int i = t; i < 4 * KK; i += 256)
        Wsh[i] = W[(l0 + i / KK) * wsz + c * KK + (i % KK)];
    for (int i = t; i < 72 * 72; i += 256) Xs[i] = 0.f;
    __syncthreads();
    for (int i = t; i < 4096; i += 256) {
        int gr = i >> 6, gc = i & 63;
        int g = gc + 3;
        Xs[(gr + 3) * 72 + (g & 1) * 36 + (g >> 1)] = X[i];
    }
    __syncthreads();

    int rowbase[4];
    int P = KS / 2;
#pragma unroll
    for (int r = 0; r < 4; r++) {
        int idx = t + r * 256;
        int oy = idx >> 5, ox = idx & 31;
        rowbase[r] = (2 * oy + 3 - P) * 72 + ox;
    }

    float acc[4][4];
#pragma unroll
    for (int r = 0; r < 4; r++)
#pragma unroll
        for (int ff = 0; ff < 4; ff++) acc[r][ff] = 0.f;

    if (bank == 0)      conv_group<3>(Xs, Wsh, rowbase, acc);
    else if (bank == 1) conv_group<5>(Xs, Wsh, rowbase, acc);
    else                conv_group<7>(Xs, Wsh, rowbase, acc);

    float* outp = src ? g_yp[c] : g_xp[c];
#pragma unroll
    for (int ff = 0; ff < 4; ff++) {
        int fg = bank * 128 + l0 + ff;
#pragma unroll
        for (int r = 0; r < 4; r++)
            outp[fg * NPTS + b * 1024 + t + r * 256] = acc[r][ff];
    }
}

// ============================================================
// Stage 2 (fused, one block per filter, 512 threads):
//   sum channel partials (fixed order) -> tau -> y-histogram
//   (32 bins, centroids, uint32 fixed-point) -> U via weighted
//   tanh -> u-histogram (256 bins, uint32) -> Bernstein p_hat
//   (interleaved conflict-free chunks) -> f_js -> g_loss[f]
// Integer atomics + fixed-order reductions => bit-deterministic.
// ============================================================
__global__ void __launch_bounds__(512) fused_kernel() {
    int f = blockIdx.x;
    int t = threadIdx.x;

    __shared__ float  ys[NPTS];                       // 8KB
    __shared__ float  r1[16], r2[16], r3[16], r4[16];
    __shared__ float  bc[4];                          // c2, bmin, yscale
    __shared__ unsigned ycnt[NHB], ysum[NHB];         // sum scale 2^14
    __shared__ float2 hb[NHB];                        // (-c2*centroid, weight)
    __shared__ unsigned ucnt[NUB], usum[NUB];         // sum scale 2^20
    __shared__ float  ulw[NUB], ul1[NUB], uw[NUB];
    __shared__ float  part[4][NBINS];
    __shared__ float  arr[128];

    for (int i = t; i < NHB; i += 512) { ycnt[i] = 0u; ysum[i] = 0u; }
    for (int i = t; i < NUB; i += 512) { ucnt[i] = 0u; usum[i] = 0u; }

    // ---- sum y channel partials (fixed order); stats ----
    const float* y0 = g_yp[0] + f * NPTS;
    const float* y1 = g_yp[1] + f * NPTS;
    const float* y2 = g_yp[2] + f * NPTS;
    float s = 0.f, ss = 0.f, mn = 1e30f, mx = -1e30f;
    for (int i = t; i < NPTS; i += 512) {
        float v = (y0[i] + y1[i]) + y2[i];
        ys[i] = v;
        s += v; ss = fmaf(v, v, ss);
        mn = fminf(mn, v); mx = fmaxf(mx, v);
    }
    for (int o = 16; o > 0; o >>= 1) {
        s  += __shfl_down_sync(0xffffffffu, s, o);
        ss += __shfl_down_sync(0xffffffffu, ss, o);
        mn  = fminf(mn, __shfl_down_sync(0xffffffffu, mn, o));
        mx  = fmaxf(mx, __shfl_down_sync(0xffffffffu, mx, o));
    }
    int w = t >> 5, lane = t & 31;
    if (lane == 0) { r1[w] = s; r2[w] = ss; r3[w] = mn; r4[w] = mx; }
    __syncthreads();

    if (t == 0) {
        float S = 0.f, SS = 0.f, MN = r3[0], MX = r4[0];
        for (int i = 0; i < 16; i++) {
            S += r1[i]; SS += r2[i];
            MN = fminf(MN, r3[i]); MX = fmaxf(MX, r4[i]);
        }
        float mean = S * (1.f / NPTS);
        float var  = (SS - (float)NPTS * mean * mean) * (1.f / (NPTS - 1));
        float sd   = sqrtf(fmaxf(var, 0.f));
        float scl  = (f < 128) ? 0.3f : (f < 256) ? 0.18f : 0.1f;
        float tau  = scl * (sd + 1e-6f) + 1e-4f;
        bc[0] = 0.5f / tau;
        bc[1] = MN;
        bc[2] = (float)NHB / ((MX - MN) * (1.f + 1e-6f) + 1e-20f);
    }
    __syncthreads();

    float c2 = bc[0], bmin = bc[1], yscale = bc[2];

    // ---- y histogram (uint32 fixed point, q scale 2^14) ----
    for (int i = t; i < NPTS; i += 512) {
        float q = (ys[i] - bmin) * yscale;
        int b = min((int)q, NHB - 1);
        atomicAdd(&ycnt[b], 1u);
        atomicAdd(&ysum[b], (unsigned)(q * 16384.0f + 0.5f));
    }
    __syncthreads();

    for (int b = t; b < NHB; b += 512) {
        unsigned c = ycnt[b];
        float cen = bmin;
        if (c > 0)
            cen = bmin + ((float)ysum[b] / (16384.0f * (float)c)) / yscale;
        hb[b] = make_float2(-c2 * cen, (float)c);
    }
    __syncthreads();

    // ---- U for 4 x-values per thread; u-histogram ----
    const float4 xa = ((const float4*)(g_xp[0] + f * NPTS))[t];
    const float4 xb = ((const float4*)(g_xp[1] + f * NPTS))[t];
    const float4 xc = ((const float4*)(g_xp[2] + f * NPTS))[t];
    float x0 = ((xa.x + xb.x) + xc.x) * c2;
    float x1 = ((xa.y + xb.y) + xc.y) * c2;
    float x2 = ((xa.z + xb.z) + xc.z) * c2;
    float x3 = ((xa.w + xb.w) + xc.w) * c2;
    float a0 = 0.f, a1 = 0.f, a2 = 0.f, a3 = 0.f;
#pragma unroll
    for (int b = 0; b < NHB; b++) {
        float2 h = hb[b];
        a0 = fmaf(h.y, tanhf_approx(h.x + x0), a0);
        a1 = fmaf(h.y, tanhf_approx(h.x + x1), a1);
        a2 = fmaf(h.y, tanhf_approx(h.x + x2), a2);
        a3 = fmaf(h.y, tanhf_approx(h.x + x3), a3);
    }
#pragma unroll
    for (int q = 0; q < 4; q++) {
        float acc = (q == 0) ? a0 : (q == 1) ? a1 : (q == 2) ? a2 : a3;
        float u = fmaf(acc, 0.5f / NPTS, 0.5f);
        u = fminf(fmaxf(u, 1e-6f), 1.f - 1e-6f);
        int b = min((int)(u * (float)NUB), NUB - 1);
        atomicAdd(&ucnt[b], 1u);
        atomicAdd(&usum[b], (unsigned)(u * 1048576.0f + 0.5f));  // 2^20
    }
    __syncthreads();

    // ---- per-u-bin log terms ----
    for (int b = t; b < NUB; b += 512) {
        unsigned c = ucnt[b];
        if (c > 0) {
            float uc = (float)usum[b] / (1048576.0f * (float)c);
            uc = fminf(fmaxf(uc, 1e-6f), 1.f - 1e-6f);
            ulw[b] = logf(uc);
            ul1[b] = logf(1.f - uc);
            uw[b]  = (float)c;
        } else {
            ulw[b] = -40.f;
            ul1[b] = -40.f;
            uw[b]  = 0.f;
        }
    }
    __syncthreads();

    // ---- Bernstein p_hat partials: 388 threads = 97 n x 4 chunks.
    // Interleaved chunks (b = ch + 4i) -> conflict-free; 2 accs.
    if (t < 4 * NBINS) {
        int n = t >> 2, ch = t & 3;
        float fn = (float)n, kn = (float)(KB - n);
        float logC = lgammaf((float)(KB + 1)) - lgammaf(fn + 1.f) - lgammaf(kn + 1.f);
        float acc0 = 0.f, acc1 = 0.f;
#pragma unroll 4
        for (int i = 0; i < NUB / 8; i++) {
            int b0 = ch + 8 * i;
            int b1 = b0 + 4;
            acc0 += uw[b0] * __expf(fmaf(fn, ulw[b0], fmaf(kn, ul1[b0], logC)));
            acc1 += uw[b1] * __expf(fmaf(fn, ulw[b1], fmaf(kn, ul1[b1], logC)));
        }
        part[ch][n] = acc0 + acc1;
    }
    __syncthreads();

    // ---- f_js per bin, then fixed-order parallel block sum ----
    float val = 0.f;
    if (t < NBINS) {
        float p = part[0][t] + part[1][t] + part[2][t] + part[3][t];
        float ph = p * (1.f / NPTS);
        float v  = fmaxf(ph * (float)NBINS, 1e-12f);
        float wv = 1.f / (1.f + v);
        float term = 0.5f * (1.f + v) *
            (0.6931471805599453f + logf(fmaxf(wv, 1e-12f)) + log1pf(-wv));
        val = term * (1.f / NBINS);
    }
    if (t < 128) arr[t] = (t < NBINS) ? val : 0.f;
    __syncthreads();
    if (t < 32) {
        float a = arr[t] + arr[t + 32] + arr[t + 64] + arr[t + 96];
        for (int o = 16; o > 0; o >>= 1)
            a += __shfl_down_sync(0xffffffffu, a, o);
        if (t == 0) g_loss[f] = a;
    }
}

// ============================================================
// Stage 3: deterministic final reduction
// ============================================================
__global__ void __launch_bounds__(512) reduce_kernel(float* out) {
    int t = threadIdx.x;
    float v = (t < NFILT) ? g_loss[t] : 0.f;
    for (int o = 16; o > 0; o >>= 1) v += __shfl_down_sync(0xffffffffu, v, o);
    __shared__ float sh[16];
    if ((t & 31) == 0) sh[t >> 5] = v;
    __syncthreads();
    if (t == 0) {
        float s = 0.f;
        for (int i = 0; i < 16; i++) s += sh[i];
        out[0] = s * (1.f / 384.f);
    }
}

extern "C" void kernel_launch(void* const* d_in, const int* in_sizes, int n_in,
                              void* d_out, int out_size) {
    const float* Xg = (const float*)d_in[0];
    const float* Xd = (const float*)d_in[1];
    const float* W3 = (const float*)d_in[2];
    const float* W5 = (const float*)d_in[3];
    const float* W7 = (const float*)d_in[4];

    conv_kernel<<<1152, 256>>>(Xg, Xd, W3, W5, W7);
    fused_kernel<<<NFILT, 512>>>();
    reduce_kernel<<<1, 512>>>((float*)d_out);
}